// round 14
// baseline (speedup 1.0000x reference)
// R12 post-mortem: LDS instruction throughput (~1/cyc/SM) was the wall —
// per-thread full-h reads scale with threads×NB. This round: 64 threads/CTA,
// each owns ALL 4 gate rows of one unit (no gate shfl, c thread-local),
// 1 batch/CTA (exact encoder early-exit), 5 CTAs/SM via __launch_bounds__.
// LDS per batch-step drops 4x; fma pipe becomes the binding resource.
#include <cuda_runtime.h>

#define Bn 4096
#define Tn 2048
#define Hn 64

// Device scratch (no allocs allowed).
__device__ float        g_partial[Bn];
__device__ int          g_perm[Bn];
__device__ unsigned int g_done = 0;   // self-resets via atomicInc wrap at Bn

// ---------- packed f32x2 helpers (FFMA2 path, sm_103a) ----------
__device__ __forceinline__ unsigned long long pack2(float x, float y) {
    unsigned long long r;
    asm("mov.b64 %0, {%1, %2};" : "=l"(r) : "f"(x), "f"(y));
    return r;
}
__device__ __forceinline__ void unpack2(unsigned long long v, float& x, float& y) {
    asm("mov.b64 {%0, %1}, %2;" : "=f"(x), "=f"(y) : "l"(v));
}
__device__ __forceinline__ void ffma2(unsigned long long& d,
                                      unsigned long long a,
                                      unsigned long long b) {
    asm("fma.rn.f32x2 %0, %1, %2, %0;" : "+l"(d) : "l"(a), "l"(b));
}
__device__ __forceinline__ unsigned long long add2(unsigned long long a,
                                                   unsigned long long b) {
    unsigned long long r;
    asm("add.rn.f32x2 %0, %1, %2;" : "=l"(r) : "l"(a), "l"(b));
    return r;
}

// ---------- activations: hardware MUFU.TANH ----------
__device__ __forceinline__ float tanh_hw(float x) {
    float r;
    asm("tanh.approx.f32 %0, %1;" : "=f"(r) : "f"(x));
    return r;
}
__device__ __forceinline__ float sigm(float x) {
    return __fmaf_rn(tanh_hw(0.5f * x), 0.5f, 0.5f);
}

// ---------- seqlen counting sort (descending) -> g_perm ----------
// Longest-first CTA scheduling; output invariant to intra-bucket order.
__global__ void sort_kernel(const int* __restrict__ seql) {
    __shared__ int off[2049];
    int t = threadIdx.x;
    for (int i = t; i < 2049; i += 1024) off[i] = 0;
    __syncthreads();
    for (int i = t; i < Bn; i += 1024) atomicAdd(&off[seql[i]], 1);
    __syncthreads();
    if (t == 0) {
        int acc = 0;
        for (int v = 2048; v >= 1; v--) { int h = off[v]; off[v] = acc; acc += h; }
    }
    __syncthreads();
    for (int i = t; i < Bn; i += 1024) {
        int p = atomicAdd(&off[seql[i]], 1);
        g_perm[p] = i;
    }
}

// ============================================================================
// One CTA (64 threads) per batch element. Thread t owns hidden unit t:
// gate rows t, 64+t, 128+t, 192+t all in-thread -> no gate exchange, cell
// state in a register. One barrier per step; h ping-pongs in SMEM (each
// thread reads the full 256B h via 16 broadcast LDS.128 -> only 32 LDS
// warp-instrs per batch-step). Decoder rank-1 fold removes y->x feedback;
// warp 0 emits y one step late. Last CTA finalizes the loss.
// ============================================================================
__global__ __launch_bounds__(64, 5)
void lstm_kernel(const float* __restrict__ padded,
                 const int*   __restrict__ seq_lengths,
                 const float* __restrict__ enc_Wih,
                 const float* __restrict__ enc_Whh,
                 const float* __restrict__ enc_b,
                 const float* __restrict__ enc_linW,
                 const float* __restrict__ enc_linb,
                 const float* __restrict__ dec_linW,
                 const float* __restrict__ dec_linb,
                 const float* __restrict__ dec_Wih,
                 const float* __restrict__ dec_Whh,
                 const float* __restrict__ dec_b,
                 const float* __restrict__ outW,
                 const float* __restrict__ outb,
                 float* __restrict__ out) {
    __shared__ float4    hb4[2][Hn / 4];   // ping-pong hidden state
    __shared__ float4    sh_ow4[Hn / 4];   // outW
    __shared__ float     xbuf[Tn];         // input sequence
    __shared__ float     sh_hz[4];         // bottleneck hz
    __shared__ unsigned  s_last;
    __shared__ double    red_s[64];
    __shared__ long long red_c[64];

    const int t    = threadIdx.x;          // unit index 0..63
    const int lane = t & 31;

    float* hb0   = (float*)hb4[0];
    float* sh_ow = (float*)sh_ow4;

    const int b = g_perm[blockIdx.x];

    // Prefetch input (and emit padded copy), init state, stage outW.
    const float* xin     = padded + (size_t)b * Tn;
    float*       out_pad = out + 1 + (size_t)b * Tn;
    for (int i = t; i < Tn; i += 64) {
        float v = xin[i];
        xbuf[i] = v;
        out_pad[i] = v;
    }
    hb0[t]   = 0.0f;
    sh_ow[t] = outW[t];

    const int sl = seq_lengths[b];

    // Encoder weights: 4 gate rows of unit t -> 128 ull in registers.
    unsigned long long w[4][32];
    float wih[4], bs[4];
#pragma unroll
    for (int r = 0; r < 4; r++) {
        const int row = r * Hn + t;
        const float4* wp = (const float4*)(enc_Whh + row * Hn);
#pragma unroll
        for (int k = 0; k < 16; k++) {
            float4 v = wp[k];
            w[r][2 * k]     = pack2(v.x, v.y);
            w[r][2 * k + 1] = pack2(v.z, v.w);
        }
        wih[r] = enc_Wih[row];
        bs[r]  = enc_b[row];
    }
    float c_reg = 0.0f;

    __syncthreads();

    // ---- encoder: state freezes at sl -> stop exactly there ----
    for (int s = 0; s < sl; s++) {
        const ulonglong2* hq = (const ulonglong2*)hb4[s & 1];
        float* wout = (float*)hb4[(s + 1) & 1];

        unsigned long long a00 = 0ull, a01 = 0ull, a10 = 0ull, a11 = 0ull;
        unsigned long long a20 = 0ull, a21 = 0ull, a30 = 0ull, a31 = 0ull;
#pragma unroll
        for (int k = 0; k < 16; k++) {
            ulonglong2 hv = hq[k];         // broadcast LDS.128
            ffma2(a00, w[0][2 * k], hv.x); ffma2(a01, w[0][2 * k + 1], hv.y);
            ffma2(a10, w[1][2 * k], hv.x); ffma2(a11, w[1][2 * k + 1], hv.y);
            ffma2(a20, w[2][2 * k], hv.x); ffma2(a21, w[2][2 * k + 1], hv.y);
            ffma2(a30, w[3][2 * k], hv.x); ffma2(a31, w[3][2 * k + 1], hv.y);
        }
        float x = xbuf[s];
        float p0, p1;
        unpack2(add2(a00, a01), p0, p1);
        float gi = (p0 + p1) + __fmaf_rn(x, wih[0], bs[0]);
        unpack2(add2(a10, a11), p0, p1);
        float gf = (p0 + p1) + __fmaf_rn(x, wih[1], bs[1]);
        unpack2(add2(a20, a21), p0, p1);
        float gg = (p0 + p1) + __fmaf_rn(x, wih[2], bs[2]);
        unpack2(add2(a30, a31), p0, p1);
        float go = (p0 + p1) + __fmaf_rn(x, wih[3], bs[3]);

        c_reg = __fmaf_rn(sigm(gf), c_reg, sigm(gi) * tanh_hw(gg));
        wout[t] = sigm(go) * tanh_hw(c_reg);
        __syncthreads();
    }

    // ---- bottleneck: hz = sigmoid(h @ enc_linW.T + enc_linb) ----
    const float* hfin = (const float*)hb4[sl & 1];
    if (t < 3) {
        float s = enc_linb[t];
        const float* wl = enc_linW + t * Hn;
#pragma unroll 16
        for (int j = 0; j < Hn; j++) s = __fmaf_rn(wl[j], hfin[j], s);
        float z = sigm(s);
        sh_hz[t] = z;
        out[1 + 2 * (size_t)Bn * Tn + (size_t)b * 3 + t] = z;
    }
    __syncthreads();                       // hfin reads done before overwrite

    // hd = hz @ dec_linW.T + dec_linb  -> slot 0 (c carries over).
    hb0[t] = dec_linb[t]
           + dec_linW[t * 3 + 0] * sh_hz[0]
           + dec_linW[t * 3 + 1] * sh_hz[1]
           + dec_linW[t * 3 + 2] * sh_hz[2];

    // Decoder weights, FOLDED: W' = dec_Whh + dec_Wih (x) outW,
    // b' = dec_b + dec_Wih*outb.  Removes y->x from the critical path.
    float ob = outb[0];
    float wih2[4];
#pragma unroll
    for (int r = 0; r < 4; r++) {
        const int row = r * Hn + t;
        wih2[r] = dec_Wih[row];
        const float4* wp = (const float4*)(dec_Whh + row * Hn);
#pragma unroll
        for (int k = 0; k < 16; k++) {
            float4 v = wp[k], o = sh_ow4[k];
            w[r][2 * k]     = pack2(__fmaf_rn(wih2[r], o.x, v.x),
                                    __fmaf_rn(wih2[r], o.y, v.y));
            w[r][2 * k + 1] = pack2(__fmaf_rn(wih2[r], o.z, v.z),
                                    __fmaf_rn(wih2[r], o.w, v.w));
        }
        bs[r] = __fmaf_rn(wih2[r], ob, dec_b[row]);
    }

    float ow0 = sh_ow[lane];
    float ow1 = sh_ow[lane + 32];
    __syncthreads();                       // hb0 (hd) visible to all

    // qs = outW . hd + outb  (step-0 correction: true x_0 = 0, not y(hd)).
    float qs = ob;
#pragma unroll 16
    for (int j = 0; j < Hn; j++) qs = __fmaf_rn(sh_ow[j], hb0[j], qs);

    // ---- decoder: T steps of pure recurrence; warp 0 emits y one step late ----
    float  lacc  = 0.0f;
    float* out_y = out + 1 + (size_t)Bn * Tn + (size_t)b * Tn;

    for (int s = 0; s < Tn; s++) {
        const ulonglong2* hq = (const ulonglong2*)hb4[s & 1];
        float* wout = (float*)hb4[(s + 1) & 1];

        // y_{s-1} = outW . h_s + ob  (warp 0, off the critical path).
        if (t < 32 && s > 0) {
            const float* hr = (const float*)hb4[s & 1];
            float yp = hr[lane] * ow0 + hr[lane + 32] * ow1;
            yp += __shfl_xor_sync(0xffffffffu, yp, 16);
            yp += __shfl_xor_sync(0xffffffffu, yp, 8);
            yp += __shfl_xor_sync(0xffffffffu, yp, 4);
            yp += __shfl_xor_sync(0xffffffffu, yp, 2);
            yp += __shfl_xor_sync(0xffffffffu, yp, 1);
            if (t == 0) {
                float y = yp + ob;
                out_y[s - 1] = y;
                if (s - 1 < sl) {
                    float d = xbuf[s - 1] - y;
                    lacc = __fmaf_rn(d, d, lacc);
                }
            }
        }

        unsigned long long a00 = 0ull, a01 = 0ull, a10 = 0ull, a11 = 0ull;
        unsigned long long a20 = 0ull, a21 = 0ull, a30 = 0ull, a31 = 0ull;
#pragma unroll
        for (int k = 0; k < 16; k++) {
            ulonglong2 hv = hq[k];
            ffma2(a00, w[0][2 * k], hv.x); ffma2(a01, w[0][2 * k + 1], hv.y);
            ffma2(a10, w[1][2 * k], hv.x); ffma2(a11, w[1][2 * k + 1], hv.y);
            ffma2(a20, w[2][2 * k], hv.x); ffma2(a21, w[2][2 * k + 1], hv.y);
            ffma2(a30, w[3][2 * k], hv.x); ffma2(a31, w[3][2 * k + 1], hv.y);
        }
        float p0, p1;
        unpack2(add2(a00, a01), p0, p1);
        float gi = (p0 + p1) + bs[0];
        unpack2(add2(a10, a11), p0, p1);
        float gf = (p0 + p1) + bs[1];
        unpack2(add2(a20, a21), p0, p1);
        float gg = (p0 + p1) + bs[2];
        unpack2(add2(a30, a31), p0, p1);
        float go = (p0 + p1) + bs[3];
        if (s == 0) {                      // undo fold: x_0 = 0
            gi = __fmaf_rn(-wih2[0], qs, gi);
            gf = __fmaf_rn(-wih2[1], qs, gf);
            gg = __fmaf_rn(-wih2[2], qs, gg);
            go = __fmaf_rn(-wih2[3], qs, go);
        }

        c_reg = __fmaf_rn(sigm(gf), c_reg, sigm(gi) * tanh_hw(gg));
        wout[t] = sigm(go) * tanh_hw(c_reg);
        __syncthreads();
    }

    // Tail: y_{T-1} from slot Tn&1 = 0.
    if (t < 32) {
        const float* hr = (const float*)hb4[Tn & 1];
        float yp = hr[lane] * ow0 + hr[lane + 32] * ow1;
        yp += __shfl_xor_sync(0xffffffffu, yp, 16);
        yp += __shfl_xor_sync(0xffffffffu, yp, 8);
        yp += __shfl_xor_sync(0xffffffffu, yp, 4);
        yp += __shfl_xor_sync(0xffffffffu, yp, 2);
        yp += __shfl_xor_sync(0xffffffffu, yp, 1);
        if (t == 0) {
            float y = yp + ob;
            out_y[Tn - 1] = y;
            if (Tn - 1 < sl) {
                float d = xbuf[Tn - 1] - y;
                lacc = __fmaf_rn(d, d, lacc);
            }
            g_partial[b] = lacc;
        }
    }

    // ---- last-CTA deterministic loss finalize ----
    __threadfence();
    if (t == 0) s_last = atomicInc(&g_done, Bn - 1);   // wraps to 0 each run
    __syncthreads();
    if (s_last == Bn - 1) {
        __threadfence();
        double    s = 0.0;
        long long c = 0;
        for (int i = t; i < Bn; i += 64) {             // fixed order
            s += (double)g_partial[i];
            c += (long long)seq_lengths[i];
        }
        red_s[t] = s;
        red_c[t] = c;
        __syncthreads();
        for (int off = 32; off; off >>= 1) {           // fixed tree
            if (t < off) {
                red_s[t] += red_s[t + off];
                red_c[t] += red_c[t + off];
            }
            __syncthreads();
        }
        if (t == 0) out[0] = (float)(red_s[0] / (double)red_c[0]);
    }
}

extern "C" void kernel_launch(void* const* d_in, const int* in_sizes, int n_in,
                              void* d_out, int out_size) {
    const float* padded   = (const float*)d_in[0];
    const int*   seql     = (const int*)  d_in[1];
    const float* enc_Wih  = (const float*)d_in[2];
    const float* enc_Whh  = (const float*)d_in[3];
    const float* enc_b    = (const float*)d_in[4];
    const float* enc_linW = (const float*)d_in[5];
    const float* enc_linb = (const float*)d_in[6];
    const float* dec_linW = (const float*)d_in[7];
    const float* dec_linb = (const float*)d_in[8];
    const float* dec_Wih  = (const float*)d_in[9];
    const float* dec_Whh  = (const float*)d_in[10];
    const float* dec_b    = (const float*)d_in[11];
    const float* outW     = (const float*)d_in[12];
    const float* outb     = (const float*)d_in[13];
    float* out = (float*)d_out;

    sort_kernel<<<1, 1024>>>(seql);
    lstm_kernel<<<Bn, 64>>>(padded, seql,
                            enc_Wih, enc_Whh, enc_b,
                            enc_linW, enc_linb,
                            dec_linW, dec_linb,
                            dec_Wih, dec_Whh, dec_b,
                            outW, outb, out);
}

// round 15
// speedup vs baseline: 2.2487x; 2.2487x over previous
// R14 post-mortem: w[4][32] = 256 regs -> catastrophic spill. Correct geometry:
// 256 threads (weights 64 regs invariant), quad-K-split (LDS 32/batch-step,
// 4x under ceiling), NB=2, occ2 -> 16 warps/SM, 4 recurrences/SM.
#include <cuda_runtime.h>

#define Bn 4096
#define Tn 2048
#define Hn 64
#define NCTA (Bn / 2)

// Device scratch (no allocs allowed).
__device__ float        g_partial[Bn];
__device__ int          g_perm[Bn];
__device__ unsigned int g_done = 0;   // self-resets via atomicInc wrap at NCTA

// ---------- packed f32x2 helpers (FFMA2 path, sm_103a) ----------
__device__ __forceinline__ unsigned long long pack2(float x, float y) {
    unsigned long long r;
    asm("mov.b64 %0, {%1, %2};" : "=l"(r) : "f"(x), "f"(y));
    return r;
}
__device__ __forceinline__ void unpack2(unsigned long long v, float& x, float& y) {
    asm("mov.b64 {%0, %1}, %2;" : "=f"(x), "=f"(y) : "l"(v));
}
__device__ __forceinline__ void ffma2(unsigned long long& d,
                                      unsigned long long a,
                                      unsigned long long b) {
    asm("fma.rn.f32x2 %0, %1, %2, %0;" : "+l"(d) : "l"(a), "l"(b));
}

// ---------- activations: hardware MUFU.TANH ----------
__device__ __forceinline__ float tanh_hw(float x) {
    float r;
    asm("tanh.approx.f32 %0, %1;" : "=f"(r) : "f"(x));
    return r;
}
__device__ __forceinline__ float sigm(float x) {
    return __fmaf_rn(tanh_hw(0.5f * x), 0.5f, 0.5f);
}

// ---------- seqlen counting sort (descending) -> g_perm ----------
__global__ void sort_kernel(const int* __restrict__ seql) {
    __shared__ int off[2049];
    int t = threadIdx.x;
    for (int i = t; i < 2049; i += 1024) off[i] = 0;
    __syncthreads();
    for (int i = t; i < Bn; i += 1024) atomicAdd(&off[seql[i]], 1);
    __syncthreads();
    if (t == 0) {
        int acc = 0;
        for (int v = 2048; v >= 1; v--) { int h = off[v]; off[v] = acc; acc += h; }
    }
    __syncthreads();
    for (int i = t; i < Bn; i += 1024) {
        int p = atomicAdd(&off[seql[i]], 1);
        g_perm[p] = i;
    }
}

// ============================================================================
// One CTA (256 threads) per PAIR of batch elements (sorted-adjacent lengths).
// Quad of threads (qi = t&3) owns unit u = t>>2: quad row r (0..3 = i,f,g,o)
// is row r*64+u. Each thread covers h-elems [16qi, 16qi+16) for ALL 4 rows
// (4 LDS.128/batch, bank-conflict-free), then a 2-stage shfl_xor butterfly
// finishes the dots: thread qi ends with full row rf = 2*(qi&1)+(qi>>1).
// Activation 1 MUFU/thread; 3 shfl gather to qi==0 lane for the c update.
// Weights register-resident (64 regs), shared by both batch recurrences.
// Decoder rank-1 fold removes y->x feedback; warps 0/1 emit y one step late.
// ============================================================================
__global__ __launch_bounds__(256, 2)
void lstm_kernel(const float* __restrict__ padded,
                 const int*   __restrict__ seq_lengths,
                 const float* __restrict__ enc_Wih,
                 const float* __restrict__ enc_Whh,
                 const float* __restrict__ enc_b,
                 const float* __restrict__ enc_linW,
                 const float* __restrict__ enc_linb,
                 const float* __restrict__ dec_linW,
                 const float* __restrict__ dec_linb,
                 const float* __restrict__ dec_Wih,
                 const float* __restrict__ dec_Whh,
                 const float* __restrict__ dec_b,
                 const float* __restrict__ outW,
                 const float* __restrict__ outb,
                 float* __restrict__ out) {
    __shared__ float4    hb4[2][2][Hn / 4];  // [batch][slot] ping-pong h
    __shared__ float4    sh_ow4[Hn / 4];     // outW
    __shared__ float     xbuf[2][Tn];        // both input sequences
    __shared__ float     sh_hz[2][4];        // bottleneck hz
    __shared__ unsigned  s_last;
    __shared__ double    red_s[256];
    __shared__ long long red_c[256];

    const int t    = threadIdx.x;
    const int u    = t >> 2;                 // hidden unit
    const int qi   = t & 3;                  // quad lane
    const int lane = t & 31;
    const int wid  = t >> 5;
    const int rf   = 2 * (qi & 1) + ((qi >> 1) & 1);  // final row after butterfly
    const int rowf = rf * Hn + u;

    float* sh_ow = (float*)sh_ow4;

    const int b0 = g_perm[2 * blockIdx.x];
    const int b1 = g_perm[2 * blockIdx.x + 1];

    // Prefetch both sequences (and emit padded copies), init state, stage outW.
    {
        const float* x0 = padded + (size_t)b0 * Tn;
        const float* x1 = padded + (size_t)b1 * Tn;
        float* o0 = out + 1 + (size_t)b0 * Tn;
        float* o1 = out + 1 + (size_t)b1 * Tn;
        for (int i = t; i < Tn; i += 256) {
            float v0 = x0[i], v1 = x1[i];
            xbuf[0][i] = v0; o0[i] = v0;
            xbuf[1][i] = v1; o1[i] = v1;
        }
    }
    if (t < Hn) {
        ((float*)hb4[0][0])[t] = 0.0f;
        ((float*)hb4[1][0])[t] = 0.0f;
        sh_ow[t] = outW[t];
    }
    const int sl0 = seq_lengths[b0];
    const int sl1 = seq_lengths[b1];
    const int smax = max(sl0, sl1);

    // Encoder weights: 4 quad rows x 16-elem quarter -> 32 ull = 64 regs.
    unsigned long long w[4][8];
#pragma unroll
    for (int r = 0; r < 4; r++) {
        const float4* wp = (const float4*)(enc_Whh + (r * Hn + u) * Hn) + 4 * qi;
#pragma unroll
        for (int m = 0; m < 4; m++) {
            float4 v = wp[m];
            w[r][2 * m]     = pack2(v.x, v.y);
            w[r][2 * m + 1] = pack2(v.z, v.w);
        }
    }
    float wihf  = enc_Wih[rowf];
    float biasf = enc_b[rowf];
    float c0 = 0.0f, c1 = 0.0f;              // cell state (qi==0 lanes)
    float hc0 = 0.0f, hc1 = 0.0f;            // freeze-forwarded h of unit u

    __syncthreads();

    // ---- encoder: run to max(sl0,sl1); per-batch state freeze ----
    for (int s = 0; s < smax; s++) {
        const ulonglong2* hq0 = (const ulonglong2*)hb4[0][s & 1] + 4 * qi;
        const ulonglong2* hq1 = (const ulonglong2*)hb4[1][s & 1] + 4 * qi;

        unsigned long long a00 = 0ull, a01 = 0ull, a02 = 0ull, a03 = 0ull;
        unsigned long long a10 = 0ull, a11 = 0ull, a12 = 0ull, a13 = 0ull;
#pragma unroll
        for (int i = 0; i < 4; i++) {
            ulonglong2 h0 = hq0[i];          // conflict-free 4-address LDS.128
            ulonglong2 h1 = hq1[i];
            ffma2(a00, w[0][2 * i], h0.x); ffma2(a00, w[0][2 * i + 1], h0.y);
            ffma2(a01, w[1][2 * i], h0.x); ffma2(a01, w[1][2 * i + 1], h0.y);
            ffma2(a02, w[2][2 * i], h0.x); ffma2(a02, w[2][2 * i + 1], h0.y);
            ffma2(a03, w[3][2 * i], h0.x); ffma2(a03, w[3][2 * i + 1], h0.y);
            ffma2(a10, w[0][2 * i], h1.x); ffma2(a10, w[0][2 * i + 1], h1.y);
            ffma2(a11, w[1][2 * i], h1.x); ffma2(a11, w[1][2 * i + 1], h1.y);
            ffma2(a12, w[2][2 * i], h1.x); ffma2(a12, w[2][2 * i + 1], h1.y);
            ffma2(a13, w[3][2 * i], h1.x); ffma2(a13, w[3][2 * i + 1], h1.y);
        }

#pragma unroll
        for (int j = 0; j < 2; j++) {
            float p0, p1, p2, p3, lo, hi;
            unpack2(j ? a10 : a00, lo, hi); p0 = lo + hi;
            unpack2(j ? a11 : a01, lo, hi); p1 = lo + hi;
            unpack2(j ? a12 : a02, lo, hi); p2 = lo + hi;
            unpack2(j ? a13 : a03, lo, hi); p3 = lo + hi;

            // 2-stage butterfly: qi ends with full sum of row rf.
            float s0 = (qi & 1) ? p2 : p0,  o0 = (qi & 1) ? p0 : p2;
            float s1 = (qi & 1) ? p3 : p1,  o1 = (qi & 1) ? p1 : p3;
            s0 += __shfl_xor_sync(0xffffffffu, o0, 1);
            s1 += __shfl_xor_sync(0xffffffffu, o1, 1);
            float f0 = (qi & 2) ? s1 : s0,  f1 = (qi & 2) ? s0 : s1;
            float gsum = f0 + __shfl_xor_sync(0xffffffffu, f1, 2);

            float gv = gsum + __fmaf_rn(xbuf[j][s], wihf, biasf);
            // rf==2 (tanh row) <=> qi==1
            float av = (qi == 1) ? tanh_hw(gv)
                                 : __fmaf_rn(tanh_hw(0.5f * gv), 0.5f, 0.5f);
            float gt = __shfl_xor_sync(0xffffffffu, av, 1);  // qi0 <- tanh(g)
            float fs = __shfl_xor_sync(0xffffffffu, av, 2);  // qi0 <- sig(f)
            float os = __shfl_xor_sync(0xffffffffu, av, 3);  // qi0 <- sig(o)
            if (qi == 0) {
                float& c  = j ? c1 : c0;
                float& hc = j ? hc1 : hc0;
                if (s < (j ? sl1 : sl0)) {
                    c  = __fmaf_rn(fs, c, av * gt);
                    hc = os * tanh_hw(c);
                }
                ((float*)hb4[j][(s + 1) & 1])[u] = hc;
            }
        }
        __syncthreads();
    }

    // ---- bottleneck: warp 0 -> b0, warp 1 -> b1 (lanes 0..2) ----
    if (wid < 2 && lane < 3) {
        const float* hf = (const float*)hb4[wid][smax & 1];
        float s = enc_linb[lane];
        const float* wl = enc_linW + lane * Hn;
#pragma unroll 16
        for (int j = 0; j < Hn; j++) s = __fmaf_rn(wl[j], hf[j], s);
        float z = sigm(s);
        sh_hz[wid][lane] = z;
        out[1 + 2 * (size_t)Bn * Tn + (size_t)(wid ? b1 : b0) * 3 + lane] = z;
    }
    __syncthreads();

    // hd -> slot 0 per batch (c carries over). threads 0..127: j = t>>6.
    if (t < 2 * Hn) {
        int j = t >> 6, i = t & 63;
        ((float*)hb4[j][0])[i] = dec_linb[i]
            + dec_linW[i * 3 + 0] * sh_hz[j][0]
            + dec_linW[i * 3 + 1] * sh_hz[j][1]
            + dec_linW[i * 3 + 2] * sh_hz[j][2];
    }

    // Decoder weights, FOLDED: W'[row] = dec_Whh[row] + dec_Wih[row]*outW,
    // b' = dec_b + dec_Wih*outb.  (fold uses each quad row's own wih!)
#pragma unroll
    for (int r = 0; r < 4; r++) {
        const int row = r * Hn + u;
        const float  wr = dec_Wih[row];
        const float4* wp = (const float4*)(dec_Whh + row * Hn) + 4 * qi;
        const float4* op = sh_ow4 + 4 * qi;
#pragma unroll
        for (int m = 0; m < 4; m++) {
            float4 v = wp[m], o = op[m];
            w[r][2 * m]     = pack2(__fmaf_rn(wr, o.x, v.x), __fmaf_rn(wr, o.y, v.y));
            w[r][2 * m + 1] = pack2(__fmaf_rn(wr, o.z, v.z), __fmaf_rn(wr, o.w, v.w));
        }
    }
    float ob    = outb[0];
    float wih2f = dec_Wih[rowf];
    biasf = __fmaf_rn(wih2f, ob, dec_b[rowf]);

    float ow0 = sh_ow[lane];
    float ow1 = sh_ow[lane + 32];
    __syncthreads();

    // qs_j = outW . hd_j + outb (step-0 correction: true x_0 = 0).
    float qs0 = ob, qs1 = ob;
    {
        const float* hd0 = (const float*)hb4[0][0];
        const float* hd1 = (const float*)hb4[1][0];
#pragma unroll 16
        for (int j = 0; j < Hn; j++) {
            float o = sh_ow[j];
            qs0 = __fmaf_rn(o, hd0[j], qs0);
            qs1 = __fmaf_rn(o, hd1[j], qs1);
        }
    }

    // ---- decoder: T steps; warps 0/1 emit y for b0/b1 one step late ----
    float lacc = 0.0f;                       // lane0 of warps 0/1

    for (int s = 0; s < Tn; s++) {
        // lagged y projection, off the recurrence critical path
        if (s > 0 && wid < 2) {
            const float* hr = (const float*)hb4[wid][s & 1];
            float yp = hr[lane] * ow0 + hr[lane + 32] * ow1;
            yp += __shfl_xor_sync(0xffffffffu, yp, 16);
            yp += __shfl_xor_sync(0xffffffffu, yp, 8);
            yp += __shfl_xor_sync(0xffffffffu, yp, 4);
            yp += __shfl_xor_sync(0xffffffffu, yp, 2);
            yp += __shfl_xor_sync(0xffffffffu, yp, 1);
            if (lane == 0) {
                float y = yp + ob;
                int   bb = wid ? b1 : b0;
                out[1 + (size_t)Bn * Tn + (size_t)bb * Tn + (s - 1)] = y;
                if (s - 1 < (wid ? sl1 : sl0)) {
                    float d = xbuf[wid][s - 1] - y;
                    lacc = __fmaf_rn(d, d, lacc);
                }
            }
        }

        const ulonglong2* hq0 = (const ulonglong2*)hb4[0][s & 1] + 4 * qi;
        const ulonglong2* hq1 = (const ulonglong2*)hb4[1][s & 1] + 4 * qi;

        unsigned long long a00 = 0ull, a01 = 0ull, a02 = 0ull, a03 = 0ull;
        unsigned long long a10 = 0ull, a11 = 0ull, a12 = 0ull, a13 = 0ull;
#pragma unroll
        for (int i = 0; i < 4; i++) {
            ulonglong2 h0 = hq0[i];
            ulonglong2 h1 = hq1[i];
            ffma2(a00, w[0][2 * i], h0.x); ffma2(a00, w[0][2 * i + 1], h0.y);
            ffma2(a01, w[1][2 * i], h0.x); ffma2(a01, w[1][2 * i + 1], h0.y);
            ffma2(a02, w[2][2 * i], h0.x); ffma2(a02, w[2][2 * i + 1], h0.y);
            ffma2(a03, w[3][2 * i], h0.x); ffma2(a03, w[3][2 * i + 1], h0.y);
            ffma2(a10, w[0][2 * i], h1.x); ffma2(a10, w[0][2 * i + 1], h1.y);
            ffma2(a11, w[1][2 * i], h1.x); ffma2(a11, w[1][2 * i + 1], h1.y);
            ffma2(a12, w[2][2 * i], h1.x); ffma2(a12, w[2][2 * i + 1], h1.y);
            ffma2(a13, w[3][2 * i], h1.x); ffma2(a13, w[3][2 * i + 1], h1.y);
        }

#pragma unroll
        for (int j = 0; j < 2; j++) {
            float p0, p1, p2, p3, lo, hi;
            unpack2(j ? a10 : a00, lo, hi); p0 = lo + hi;
            unpack2(j ? a11 : a01, lo, hi); p1 = lo + hi;
            unpack2(j ? a12 : a02, lo, hi); p2 = lo + hi;
            unpack2(j ? a13 : a03, lo, hi); p3 = lo + hi;

            float s0 = (qi & 1) ? p2 : p0,  o0 = (qi & 1) ? p0 : p2;
            float s1 = (qi & 1) ? p3 : p1,  o1 = (qi & 1) ? p1 : p3;
            s0 += __shfl_xor_sync(0xffffffffu, o0, 1);
            s1 += __shfl_xor_sync(0xffffffffu, o1, 1);
            float f0 = (qi & 2) ? s1 : s0,  f1 = (qi & 2) ? s0 : s1;
            float gsum = f0 + __shfl_xor_sync(0xffffffffu, f1, 2);

            float gv = gsum + biasf;
            if (s == 0) gv = __fmaf_rn(-wih2f, j ? qs1 : qs0, gv);

            float av = (qi == 1) ? tanh_hw(gv)
                                 : __fmaf_rn(tanh_hw(0.5f * gv), 0.5f, 0.5f);
            float gt = __shfl_xor_sync(0xffffffffu, av, 1);
            float fs = __shfl_xor_sync(0xffffffffu, av, 2);
            float os = __shfl_xor_sync(0xffffffffu, av, 3);
            if (qi == 0) {
                float& c = j ? c1 : c0;
                c = __fmaf_rn(fs, c, av * gt);
                ((float*)hb4[j][(s + 1) & 1])[u] = os * tanh_hw(c);
            }
        }
        __syncthreads();
    }

    // Tail: y_{T-1} from slot Tn&1 = 0.
    if (wid < 2) {
        const float* hr = (const float*)hb4[wid][Tn & 1];
        float yp = hr[lane] * ow0 + hr[lane + 32] * ow1;
        yp += __shfl_xor_sync(0xffffffffu, yp, 16);
        yp += __shfl_xor_sync(0xffffffffu, yp, 8);
        yp += __shfl_xor_sync(0xffffffffu, yp, 4);
        yp += __shfl_xor_sync(0xffffffffu, yp, 2);
        yp += __shfl_xor_sync(0xffffffffu, yp, 1);
        if (lane == 0) {
            float y = yp + ob;
            int   bb = wid ? b1 : b0;
            out[1 + (size_t)Bn * Tn + (size_t)bb * Tn + (Tn - 1)] = y;
            if (Tn - 1 < (wid ? sl1 : sl0)) {
                float d = xbuf[wid][Tn - 1] - y;
                lacc = __fmaf_rn(d, d, lacc);
            }
            g_partial[bb] = lacc;
        }
    }

    // ---- last-CTA deterministic loss finalize ----
    __threadfence();
    if (t == 0) s_last = atomicInc(&g_done, NCTA - 1);   // wraps to 0 each run
    __syncthreads();
    if (s_last == NCTA - 1) {
        __threadfence();
        double    s = 0.0;
        long long c = 0;
        for (int i = t; i < Bn; i += 256) {              // fixed order
            s += (double)g_partial[i];
            c += (long long)seq_lengths[i];
        }
        red_s[t] = s;
        red_c[t] = c;
        __syncthreads();
        for (int off = 128; off; off >>= 1) {            // fixed tree
            if (t < off) {
                red_s[t] += red_s[t + off];
                red_c[t] += red_c[t + off];
            }
            __syncthreads();
        }
        if (t == 0) out[0] = (float)(red_s[0] / (double)red_c[0]);
    }
}

extern "C" void kernel_launch(void* const* d_in, const int* in_sizes, int n_in,
                              void* d_out, int out_size) {
    const float* padded   = (const float*)d_in[0];
    const int*   seql     = (const int*)  d_in[1];
    const float* enc_Wih  = (const float*)d_in[2];
    const float* enc_Whh  = (const float*)d_in[3];
    const float* enc_b    = (const float*)d_in[4];
    const float* enc_linW = (const float*)d_in[5];
    const float* enc_linb = (const float*)d_in[6];
    const float* dec_linW = (const float*)d_in[7];
    const float* dec_linb = (const float*)d_in[8];
    const float* dec_Wih  = (const float*)d_in[9];
    const float* dec_Whh  = (const float*)d_in[10];
    const float* dec_b    = (const float*)d_in[11];
    const float* outW     = (const float*)d_in[12];
    const float* outb     = (const float*)d_in[13];
    float* out = (float*)d_out;

    sort_kernel<<<1, 1024>>>(seql);
    lstm_kernel<<<NCTA, 256>>>(padded, seql,
                               enc_Wih, enc_Whh, enc_b,
                               enc_linW, enc_linb,
                               dec_linW, dec_linb,
                               dec_Wih, dec_Whh, dec_b,
                               outW, outb, out);
}

// round 16
// speedup vs baseline: 3.3553x; 1.4921x over previous
// R15 post-mortem: SHFL shares the MIO pipe with LDS — quad-split made MIO
// worse. R11 (128thr, 2 rows/thread, pair exchange) is the measured-best
// tail/MIO shape. This round: R11 + third batch per CTA (NB=3) for in-warp
// ILP; single accumulator per (row,batch) to hold regs ~230 (occ2, cap 255).
#include <cuda_runtime.h>

#define Bn 4096
#define Tn 2048
#define Hn 64
#define NB 3
#define NCTA ((Bn + NB - 1) / NB)   // 1366

// Device scratch (no allocs allowed).
__device__ float        g_partial[Bn];
__device__ int          g_perm[Bn];
__device__ unsigned int g_done = 0;   // self-resets via atomicInc wrap at NCTA

// ---------- packed f32x2 helpers (FFMA2 path, sm_103a) ----------
__device__ __forceinline__ unsigned long long pack2(float x, float y) {
    unsigned long long r;
    asm("mov.b64 %0, {%1, %2};" : "=l"(r) : "f"(x), "f"(y));
    return r;
}
__device__ __forceinline__ void unpack2(unsigned long long v, float& x, float& y) {
    asm("mov.b64 {%0, %1}, %2;" : "=f"(x), "=f"(y) : "l"(v));
}
__device__ __forceinline__ void ffma2(unsigned long long& d,
                                      unsigned long long a,
                                      unsigned long long b) {
    asm("fma.rn.f32x2 %0, %1, %2, %0;" : "+l"(d) : "l"(a), "l"(b));
}

// ---------- activations: hardware MUFU.TANH ----------
__device__ __forceinline__ float tanh_hw(float x) {
    float r;
    asm("tanh.approx.f32 %0, %1;" : "=f"(r) : "f"(x));
    return r;
}
__device__ __forceinline__ float sigm(float x) {
    return __fmaf_rn(tanh_hw(0.5f * x), 0.5f, 0.5f);
}

// ---------- seqlen counting sort (descending) -> g_perm ----------
__global__ void sort_kernel(const int* __restrict__ seql) {
    __shared__ int off[2049];
    int t = threadIdx.x;
    for (int i = t; i < 2049; i += 1024) off[i] = 0;
    __syncthreads();
    for (int i = t; i < Bn; i += 1024) atomicAdd(&off[seql[i]], 1);
    __syncthreads();
    if (t == 0) {
        int acc = 0;
        for (int v = 2048; v >= 1; v--) { int h = off[v]; off[v] = acc; acc += h; }
    }
    __syncthreads();
    for (int i = t; i < Bn; i += 1024) {
        int p = atomicAdd(&off[seql[i]], 1);
        g_perm[p] = i;
    }
}

// ============================================================================
// One CTA (128 threads) per TRIPLE of batch elements (sorted-adjacent lens).
// Thread pair (2u,2u+1) owns unit u: even thread -> rows (u, 64+u) = (i,f),
// odd -> (128+u, 192+u) = (g,o). Weights register-resident (128 regs),
// shared by all 3 recurrences; single f32x2 accumulator per (row,batch)
// (6 chains, 6-instr interleave >= rt). Pair exchange = 2 shfl_xor(1).
// One barrier per step-triple; per-batch ping-pong h. Decoder rank-1 fold
// removes y->x; warps 0/1/2 emit y for b0/b1/b2 one step late.
// ============================================================================
__global__ __launch_bounds__(128, 2)
void lstm_kernel(const float* __restrict__ padded,
                 const int*   __restrict__ seq_lengths,
                 const float* __restrict__ enc_Wih,
                 const float* __restrict__ enc_Whh,
                 const float* __restrict__ enc_b,
                 const float* __restrict__ enc_linW,
                 const float* __restrict__ enc_linb,
                 const float* __restrict__ dec_linW,
                 const float* __restrict__ dec_linb,
                 const float* __restrict__ dec_Wih,
                 const float* __restrict__ dec_Whh,
                 const float* __restrict__ dec_b,
                 const float* __restrict__ outW,
                 const float* __restrict__ outb,
                 float* __restrict__ out) {
    __shared__ float4    hb4[NB][2][Hn / 4];  // [batch][slot] ping-pong h
    __shared__ float4    sh_ow4[Hn / 4];      // outW
    __shared__ float     xbuf[NB][Tn];        // input sequences
    __shared__ float     sh_hz[NB][4];        // bottleneck hz
    __shared__ unsigned  s_last;
    __shared__ double    red_s[128];
    __shared__ long long red_c[128];

    const int  t    = threadIdx.x;
    const int  u    = t >> 1;
    const bool even = !(t & 1);
    const int  lane = t & 31;
    const int  wid  = t >> 5;

    float* sh_ow = (float*)sh_ow4;

    const int rA = even ? u      : 128 + u;
    const int rB = even ? 64 + u : 192 + u;

    int  bs_[NB];
    bool val[NB];
    int  sl[NB];
#pragma unroll
    for (int j = 0; j < NB; j++) {
        int idx = NB * blockIdx.x + j;
        val[j] = (idx < Bn);
        bs_[j] = g_perm[val[j] ? idx : 0];
        sl[j]  = val[j] ? seq_lengths[bs_[j]] : 0;
    }
    const int smax = max(sl[0], max(sl[1], sl[2]));

    // Prefetch sequences (+ emit padded copies), init state, stage outW.
    for (int i = t; i < Tn; i += 128) {
#pragma unroll
        for (int j = 0; j < NB; j++) {
            float v = padded[(size_t)bs_[j] * Tn + i];
            xbuf[j][i] = v;
            if (val[j]) out[1 + (size_t)bs_[j] * Tn + i] = v;
        }
    }
    if (t < Hn) {
#pragma unroll
        for (int j = 0; j < NB; j++) ((float*)hb4[j][0])[t] = 0.0f;
        sh_ow[t] = outW[t];
    }

    // Encoder weights: 2 rows x 64 floats = 64 ull in registers.
    unsigned long long wA[32], wB[32];
    {
        const float4* pA = (const float4*)(enc_Whh + rA * Hn);
        const float4* pB = (const float4*)(enc_Whh + rB * Hn);
#pragma unroll
        for (int k = 0; k < 16; k++) {
            float4 a = pA[k];
            wA[2 * k]     = pack2(a.x, a.y);
            wA[2 * k + 1] = pack2(a.z, a.w);
            float4 c = pB[k];
            wB[2 * k]     = pack2(c.x, c.y);
            wB[2 * k + 1] = pack2(c.z, c.w);
        }
    }
    float wihA = enc_Wih[rA], wihB = enc_Wih[rB];
    float bsA  = enc_b[rA],   bsB  = enc_b[rB];
    float c_[NB]  = {0.0f, 0.0f, 0.0f};    // cell state (replicated in pair)
    float hc_[NB] = {0.0f, 0.0f, 0.0f};    // freeze-forwarded h of unit u

    __syncthreads();

    // ---- encoder: run to max seqlen; per-batch state freeze ----
    for (int s = 0; s < smax; s++) {
        const ulonglong2* hq0 = (const ulonglong2*)hb4[0][s & 1];
        const ulonglong2* hq1 = (const ulonglong2*)hb4[1][s & 1];
        const ulonglong2* hq2 = (const ulonglong2*)hb4[2][s & 1];

        unsigned long long aA[NB], aB[NB];
#pragma unroll
        for (int j = 0; j < NB; j++) { aA[j] = 0ull; aB[j] = 0ull; }

#pragma unroll
        for (int k = 0; k < 16; k++) {
            ulonglong2 h0 = hq0[k];        // broadcast LDS.128
            ulonglong2 h1 = hq1[k];
            ulonglong2 h2 = hq2[k];
            // 6 independent chains, 6-instr reuse distance per chain
            ffma2(aA[0], wA[2 * k], h0.x); ffma2(aB[0], wB[2 * k], h0.x);
            ffma2(aA[1], wA[2 * k], h1.x); ffma2(aB[1], wB[2 * k], h1.x);
            ffma2(aA[2], wA[2 * k], h2.x); ffma2(aB[2], wB[2 * k], h2.x);
            ffma2(aA[0], wA[2 * k + 1], h0.y); ffma2(aB[0], wB[2 * k + 1], h0.y);
            ffma2(aA[1], wA[2 * k + 1], h1.y); ffma2(aB[1], wB[2 * k + 1], h1.y);
            ffma2(aA[2], wA[2 * k + 1], h2.y); ffma2(aB[2], wB[2 * k + 1], h2.y);
        }

#pragma unroll
        for (int j = 0; j < NB; j++) {
            float lo, hi;
            unpack2(aA[j], lo, hi);
            float gA = (lo + hi) + __fmaf_rn(xbuf[j][s], wihA, bsA);
            unpack2(aB[j], lo, hi);
            float gB = (lo + hi) + __fmaf_rn(xbuf[j][s], wihB, bsB);

            float oA = __shfl_xor_sync(0xffffffffu, gA, 1);
            float oB = __shfl_xor_sync(0xffffffffu, gB, 1);
            float gi = even ? gA : oA;
            float gf = even ? gB : oB;
            float gg = even ? oA : gA;
            float go = even ? oB : gB;

            if (s < sl[j]) {
                c_[j]  = __fmaf_rn(sigm(gf), c_[j], sigm(gi) * tanh_hw(gg));
                hc_[j] = sigm(go) * tanh_hw(c_[j]);
            }
            if (even) ((float*)hb4[j][(s + 1) & 1])[u] = hc_[j];
        }
        __syncthreads();
    }

    // ---- bottleneck: warp j computes hz for batch j (lanes 0..2) ----
    if (wid < NB && lane < 3) {
        const float* hf = (const float*)hb4[wid][smax & 1];
        float s = enc_linb[lane];
        const float* wl = enc_linW + lane * Hn;
#pragma unroll 16
        for (int j = 0; j < Hn; j++) s = __fmaf_rn(wl[j], hf[j], s);
        float z = sigm(s);
        sh_hz[wid][lane] = z;
        if (val[wid])
            out[1 + 2 * (size_t)Bn * Tn + (size_t)bs_[wid] * 3 + lane] = z;
    }
    __syncthreads();

    // hd -> slot 0 per batch (c carries over). threads 0..127 cover 2 batches,
    // second pass covers batch 2.
    if (t < 2 * Hn) {
        int j = t >> 6, i = t & 63;
        ((float*)hb4[j][0])[i] = dec_linb[i]
            + dec_linW[i * 3 + 0] * sh_hz[j][0]
            + dec_linW[i * 3 + 1] * sh_hz[j][1]
            + dec_linW[i * 3 + 2] * sh_hz[j][2];
    }
    if (t < Hn) {
        ((float*)hb4[2][0])[t] = dec_linb[t]
            + dec_linW[t * 3 + 0] * sh_hz[2][0]
            + dec_linW[t * 3 + 1] * sh_hz[2][1]
            + dec_linW[t * 3 + 2] * sh_hz[2][2];
    }

    // Decoder weights, FOLDED: W' = dec_Whh + dec_Wih (x) outW,
    // b' = dec_b + dec_Wih*outb (shared by all batches).
    float wihA2 = dec_Wih[rA], wihB2 = dec_Wih[rB];
    {
        const float4* pA = (const float4*)(dec_Whh + rA * Hn);
        const float4* pB = (const float4*)(dec_Whh + rB * Hn);
#pragma unroll
        for (int k = 0; k < 16; k++) {
            float4 a = pA[k], c = pB[k], o = sh_ow4[k];
            wA[2 * k]     = pack2(__fmaf_rn(wihA2, o.x, a.x), __fmaf_rn(wihA2, o.y, a.y));
            wA[2 * k + 1] = pack2(__fmaf_rn(wihA2, o.z, a.z), __fmaf_rn(wihA2, o.w, a.w));
            wB[2 * k]     = pack2(__fmaf_rn(wihB2, o.x, c.x), __fmaf_rn(wihB2, o.y, c.y));
            wB[2 * k + 1] = pack2(__fmaf_rn(wihB2, o.z, c.z), __fmaf_rn(wihB2, o.w, c.w));
        }
    }
    float ob = outb[0];
    bsA = __fmaf_rn(wihA2, ob, dec_b[rA]);
    bsB = __fmaf_rn(wihB2, ob, dec_b[rB]);

    float ow0 = sh_ow[lane];
    float ow1 = sh_ow[lane + 32];
    __syncthreads();

    // qs_j = outW . hd_j + outb (step-0 correction: true x_0 = 0).
    float qs[NB] = {ob, ob, ob};
    {
        const float* hd0 = (const float*)hb4[0][0];
        const float* hd1 = (const float*)hb4[1][0];
        const float* hd2 = (const float*)hb4[2][0];
#pragma unroll 16
        for (int j = 0; j < Hn; j++) {
            float o = sh_ow[j];
            qs[0] = __fmaf_rn(o, hd0[j], qs[0]);
            qs[1] = __fmaf_rn(o, hd1[j], qs[1]);
            qs[2] = __fmaf_rn(o, hd2[j], qs[2]);
        }
    }

    // ---- decoder: T steps; warps 0/1/2 emit y for b0/b1/b2 one step late ----
    float lacc = 0.0f;                     // lane0 of warps 0..2

    for (int s = 0; s < Tn; s++) {
        // lagged y projection, off the recurrence critical path
        if (s > 0 && wid < NB) {
            const float* hr = (const float*)hb4[wid][s & 1];
            float yp = hr[lane] * ow0 + hr[lane + 32] * ow1;
            yp += __shfl_xor_sync(0xffffffffu, yp, 16);
            yp += __shfl_xor_sync(0xffffffffu, yp, 8);
            yp += __shfl_xor_sync(0xffffffffu, yp, 4);
            yp += __shfl_xor_sync(0xffffffffu, yp, 2);
            yp += __shfl_xor_sync(0xffffffffu, yp, 1);
            if (lane == 0 && val[wid]) {
                float y = yp + ob;
                out[1 + (size_t)Bn * Tn + (size_t)bs_[wid] * Tn + (s - 1)] = y;
                if (s - 1 < sl[wid]) {
                    float d = xbuf[wid][s - 1] - y;
                    lacc = __fmaf_rn(d, d, lacc);
                }
            }
        }

        const ulonglong2* hq0 = (const ulonglong2*)hb4[0][s & 1];
        const ulonglong2* hq1 = (const ulonglong2*)hb4[1][s & 1];
        const ulonglong2* hq2 = (const ulonglong2*)hb4[2][s & 1];

        unsigned long long aA[NB], aB[NB];
#pragma unroll
        for (int j = 0; j < NB; j++) { aA[j] = 0ull; aB[j] = 0ull; }

#pragma unroll
        for (int k = 0; k < 16; k++) {
            ulonglong2 h0 = hq0[k];
            ulonglong2 h1 = hq1[k];
            ulonglong2 h2 = hq2[k];
            ffma2(aA[0], wA[2 * k], h0.x); ffma2(aB[0], wB[2 * k], h0.x);
            ffma2(aA[1], wA[2 * k], h1.x); ffma2(aB[1], wB[2 * k], h1.x);
            ffma2(aA[2], wA[2 * k], h2.x); ffma2(aB[2], wB[2 * k], h2.x);
            ffma2(aA[0], wA[2 * k + 1], h0.y); ffma2(aB[0], wB[2 * k + 1], h0.y);
            ffma2(aA[1], wA[2 * k + 1], h1.y); ffma2(aB[1], wB[2 * k + 1], h1.y);
            ffma2(aA[2], wA[2 * k + 1], h2.y); ffma2(aB[2], wB[2 * k + 1], h2.y);
        }

#pragma unroll
        for (int j = 0; j < NB; j++) {
            float lo, hi;
            unpack2(aA[j], lo, hi);
            float gA = (lo + hi) + bsA;
            unpack2(aB[j], lo, hi);
            float gB = (lo + hi) + bsB;
            if (s == 0) {                  // undo fold: x_0 = 0
                gA = __fmaf_rn(-wihA2, qs[j], gA);
                gB = __fmaf_rn(-wihB2, qs[j], gB);
            }

            float oA = __shfl_xor_sync(0xffffffffu, gA, 1);
            float oB = __shfl_xor_sync(0xffffffffu, gB, 1);
            float gi = even ? gA : oA;
            float gf = even ? gB : oB;
            float gg = even ? oA : gA;
            float go = even ? oB : gB;

            c_[j] = __fmaf_rn(sigm(gf), c_[j], sigm(gi) * tanh_hw(gg));
            if (even) ((float*)hb4[j][(s + 1) & 1])[u] = sigm(go) * tanh_hw(c_[j]);
        }
        __syncthreads();
    }

    // Tail: y_{T-1} from slot Tn&1 = 0.
    if (wid < NB) {
        const float* hr = (const float*)hb4[wid][Tn & 1];
        float yp = hr[lane] * ow0 + hr[lane + 32] * ow1;
        yp += __shfl_xor_sync(0xffffffffu, yp, 16);
        yp += __shfl_xor_sync(0xffffffffu, yp, 8);
        yp += __shfl_xor_sync(0xffffffffu, yp, 4);
        yp += __shfl_xor_sync(0xffffffffu, yp, 2);
        yp += __shfl_xor_sync(0xffffffffu, yp, 1);
        if (lane == 0 && val[wid]) {
            float y = yp + ob;
            out[1 + (size_t)Bn * Tn + (size_t)bs_[wid] * Tn + (Tn - 1)] = y;
            if (Tn - 1 < sl[wid]) {
                float d = xbuf[wid][Tn - 1] - y;
                lacc = __fmaf_rn(d, d, lacc);
            }
            g_partial[bs_[wid]] = lacc;
        }
    }

    // ---- last-CTA deterministic loss finalize ----
    __threadfence();
    if (t == 0) s_last = atomicInc(&g_done, NCTA - 1);   // wraps to 0 each run
    __syncthreads();
    if (s_last == NCTA - 1) {
        __threadfence();
        double    s = 0.0;
        long long c = 0;
        for (int i = t; i < Bn; i += 128) {              // fixed order
            s += (double)g_partial[i];
            c += (long long)seq_lengths[i];
        }
        red_s[t] = s;
        red_c[t] = c;
        __syncthreads();
        for (int off = 64; off; off >>= 1) {             // fixed tree
            if (t < off) {
                red_s[t] += red_s[t + off];
                red_c[t] += red_c[t + off];
            }
            __syncthreads();
        }
        if (t == 0) out[0] = (float)(red_s[0] / (double)red_c[0]);
    }
}

extern "C" void kernel_launch(void* const* d_in, const int* in_sizes, int n_in,
                              void* d_out, int out_size) {
    const float* padded   = (const float*)d_in[0];
    const int*   seql     = (const int*)  d_in[1];
    const float* enc_Wih  = (const float*)d_in[2];
    const float* enc_Whh  = (const float*)d_in[3];
    const float* enc_b    = (const float*)d_in[4];
    const float* enc_linW = (const float*)d_in[5];
    const float* enc_linb = (const float*)d_in[6];
    const float* dec_linW = (const float*)d_in[7];
    const float* dec_linb = (const float*)d_in[8];
    const float* dec_Wih  = (const float*)d_in[9];
    const float* dec_Whh  = (const float*)d_in[10];
    const float* dec_b    = (const float*)d_in[11];
    const float* outW     = (const float*)d_in[12];
    const float* outb     = (const float*)d_in[13];
    float* out = (float*)d_out;

    sort_kernel<<<1, 1024>>>(seql);
    lstm_kernel<<<NCTA, 128>>>(padded, seql,
                               enc_Wih, enc_Whh, enc_b,
                               enc_linW, enc_linb,
                               dec_linW, dec_linb,
                               dec_Wih, dec_Whh, dec_b,
                               outW, outb, out);
}

// round 17
// speedup vs baseline: 3.4835x; 1.0382x over previous
// R16 (11.40ms best, NB=3, fill 51%) -> NB=4 along the validated axis:
// in-warp chains 6->8, tail exposure x3/4, MIO/batch-step invariant,
// reg budget ~244 < 255 cap. 4 warps <-> 4 batches for lagged y.
#include <cuda_runtime.h>

#define Bn 4096
#define Tn 2048
#define Hn 64
#define NB 4
#define NCTA (Bn / NB)   // 1024

// Device scratch (no allocs allowed).
__device__ float        g_partial[Bn];
__device__ int          g_perm[Bn];
__device__ unsigned int g_done = 0;   // self-resets via atomicInc wrap at NCTA

// ---------- packed f32x2 helpers (FFMA2 path, sm_103a) ----------
__device__ __forceinline__ unsigned long long pack2(float x, float y) {
    unsigned long long r;
    asm("mov.b64 %0, {%1, %2};" : "=l"(r) : "f"(x), "f"(y));
    return r;
}
__device__ __forceinline__ void unpack2(unsigned long long v, float& x, float& y) {
    asm("mov.b64 {%0, %1}, %2;" : "=f"(x), "=f"(y) : "l"(v));
}
__device__ __forceinline__ void ffma2(unsigned long long& d,
                                      unsigned long long a,
                                      unsigned long long b) {
    asm("fma.rn.f32x2 %0, %1, %2, %0;" : "+l"(d) : "l"(a), "l"(b));
}

// ---------- activations: hardware MUFU.TANH ----------
__device__ __forceinline__ float tanh_hw(float x) {
    float r;
    asm("tanh.approx.f32 %0, %1;" : "=f"(r) : "f"(x));
    return r;
}
__device__ __forceinline__ float sigm(float x) {
    return __fmaf_rn(tanh_hw(0.5f * x), 0.5f, 0.5f);
}

// ---------- seqlen counting sort (descending) -> g_perm ----------
__global__ void sort_kernel(const int* __restrict__ seql) {
    __shared__ int off[2049];
    int t = threadIdx.x;
    for (int i = t; i < 2049; i += 1024) off[i] = 0;
    __syncthreads();
    for (int i = t; i < Bn; i += 1024) atomicAdd(&off[seql[i]], 1);
    __syncthreads();
    if (t == 0) {
        int acc = 0;
        for (int v = 2048; v >= 1; v--) { int h = off[v]; off[v] = acc; acc += h; }
    }
    __syncthreads();
    for (int i = t; i < Bn; i += 1024) {
        int p = atomicAdd(&off[seql[i]], 1);
        g_perm[p] = i;
    }
}

// ============================================================================
// One CTA (128 threads) per QUAD of batch elements (sorted-adjacent lens).
// Thread pair (2u,2u+1) owns unit u: even thread -> rows (u, 64+u) = (i,f),
// odd -> (128+u, 192+u) = (g,o). Weights register-resident (128 regs),
// shared by all 4 recurrences; single f32x2 accumulator per (row,batch)
// (8 chains, 8-instr interleave >= rt). Pair exchange = 2 shfl_xor(1).
// One barrier per step-quad; per-batch ping-pong h. Decoder rank-1 fold
// removes y->x; warp j emits y for batch j one step late.
// ============================================================================
__global__ __launch_bounds__(128, 2)
void lstm_kernel(const float* __restrict__ padded,
                 const int*   __restrict__ seq_lengths,
                 const float* __restrict__ enc_Wih,
                 const float* __restrict__ enc_Whh,
                 const float* __restrict__ enc_b,
                 const float* __restrict__ enc_linW,
                 const float* __restrict__ enc_linb,
                 const float* __restrict__ dec_linW,
                 const float* __restrict__ dec_linb,
                 const float* __restrict__ dec_Wih,
                 const float* __restrict__ dec_Whh,
                 const float* __restrict__ dec_b,
                 const float* __restrict__ outW,
                 const float* __restrict__ outb,
                 float* __restrict__ out) {
    __shared__ float4    hb4[NB][2][Hn / 4];  // [batch][slot] ping-pong h
    __shared__ float4    sh_ow4[Hn / 4];      // outW
    __shared__ float     xbuf[NB][Tn];        // input sequences
    __shared__ float     sh_hz[NB][4];        // bottleneck hz
    __shared__ unsigned  s_last;
    __shared__ double    red_s[128];
    __shared__ long long red_c[128];

    const int  t    = threadIdx.x;
    const int  u    = t >> 1;
    const bool even = !(t & 1);
    const int  lane = t & 31;
    const int  wid  = t >> 5;

    float* sh_ow = (float*)sh_ow4;

    const int rA = even ? u      : 128 + u;
    const int rB = even ? 64 + u : 192 + u;

    int bs_[NB];
    int sl[NB];
#pragma unroll
    for (int j = 0; j < NB; j++) {
        bs_[j] = g_perm[NB * blockIdx.x + j];     // Bn % NB == 0: always valid
        sl[j]  = seq_lengths[bs_[j]];
    }
    const int smax = max(max(sl[0], sl[1]), max(sl[2], sl[3]));

    // Prefetch sequences (+ emit padded copies), init state, stage outW.
    for (int i = t; i < Tn; i += 128) {
#pragma unroll
        for (int j = 0; j < NB; j++) {
            float v = padded[(size_t)bs_[j] * Tn + i];
            xbuf[j][i] = v;
            out[1 + (size_t)bs_[j] * Tn + i] = v;
        }
    }
    if (t < Hn) {
#pragma unroll
        for (int j = 0; j < NB; j++) ((float*)hb4[j][0])[t] = 0.0f;
        sh_ow[t] = outW[t];
    }

    // Encoder weights: 2 rows x 64 floats = 64 ull in registers.
    unsigned long long wA[32], wB[32];
    {
        const float4* pA = (const float4*)(enc_Whh + rA * Hn);
        const float4* pB = (const float4*)(enc_Whh + rB * Hn);
#pragma unroll
        for (int k = 0; k < 16; k++) {
            float4 a = pA[k];
            wA[2 * k]     = pack2(a.x, a.y);
            wA[2 * k + 1] = pack2(a.z, a.w);
            float4 c = pB[k];
            wB[2 * k]     = pack2(c.x, c.y);
            wB[2 * k + 1] = pack2(c.z, c.w);
        }
    }
    float wihA = enc_Wih[rA], wihB = enc_Wih[rB];
    float bsA  = enc_b[rA],   bsB  = enc_b[rB];
    float c_[NB]  = {0.0f, 0.0f, 0.0f, 0.0f};  // cell state (replicated in pair)
    float hc_[NB] = {0.0f, 0.0f, 0.0f, 0.0f};  // freeze-forwarded h of unit u

    __syncthreads();

    // ---- encoder: run to max seqlen; per-batch state freeze ----
    for (int s = 0; s < smax; s++) {
        const ulonglong2* hq0 = (const ulonglong2*)hb4[0][s & 1];
        const ulonglong2* hq1 = (const ulonglong2*)hb4[1][s & 1];
        const ulonglong2* hq2 = (const ulonglong2*)hb4[2][s & 1];
        const ulonglong2* hq3 = (const ulonglong2*)hb4[3][s & 1];

        unsigned long long aA[NB], aB[NB];
#pragma unroll
        for (int j = 0; j < NB; j++) { aA[j] = 0ull; aB[j] = 0ull; }

#pragma unroll
        for (int k = 0; k < 16; k++) {
            ulonglong2 h0 = hq0[k];        // broadcast LDS.128
            ulonglong2 h1 = hq1[k];
            ulonglong2 h2 = hq2[k];
            ulonglong2 h3 = hq3[k];
            // 8 independent chains, 8-instr reuse distance per chain
            ffma2(aA[0], wA[2 * k], h0.x); ffma2(aB[0], wB[2 * k], h0.x);
            ffma2(aA[1], wA[2 * k], h1.x); ffma2(aB[1], wB[2 * k], h1.x);
            ffma2(aA[2], wA[2 * k], h2.x); ffma2(aB[2], wB[2 * k], h2.x);
            ffma2(aA[3], wA[2 * k], h3.x); ffma2(aB[3], wB[2 * k], h3.x);
            ffma2(aA[0], wA[2 * k + 1], h0.y); ffma2(aB[0], wB[2 * k + 1], h0.y);
            ffma2(aA[1], wA[2 * k + 1], h1.y); ffma2(aB[1], wB[2 * k + 1], h1.y);
            ffma2(aA[2], wA[2 * k + 1], h2.y); ffma2(aB[2], wB[2 * k + 1], h2.y);
            ffma2(aA[3], wA[2 * k + 1], h3.y); ffma2(aB[3], wB[2 * k + 1], h3.y);
        }

#pragma unroll
        for (int j = 0; j < NB; j++) {
            float lo, hi;
            unpack2(aA[j], lo, hi);
            float gA = (lo + hi) + __fmaf_rn(xbuf[j][s], wihA, bsA);
            unpack2(aB[j], lo, hi);
            float gB = (lo + hi) + __fmaf_rn(xbuf[j][s], wihB, bsB);

            float oA = __shfl_xor_sync(0xffffffffu, gA, 1);
            float oB = __shfl_xor_sync(0xffffffffu, gB, 1);
            float gi = even ? gA : oA;
            float gf = even ? gB : oB;
            float gg = even ? oA : gA;
            float go = even ? oB : gB;

            if (s < sl[j]) {
                c_[j]  = __fmaf_rn(sigm(gf), c_[j], sigm(gi) * tanh_hw(gg));
                hc_[j] = sigm(go) * tanh_hw(c_[j]);
            }
            if (even) ((float*)hb4[j][(s + 1) & 1])[u] = hc_[j];
        }
        __syncthreads();
    }

    // ---- bottleneck: warp j computes hz for batch j (lanes 0..2) ----
    if (lane < 3) {
        const float* hf = (const float*)hb4[wid][smax & 1];
        float s = enc_linb[lane];
        const float* wl = enc_linW + lane * Hn;
#pragma unroll 16
        for (int j = 0; j < Hn; j++) s = __fmaf_rn(wl[j], hf[j], s);
        float z = sigm(s);
        sh_hz[wid][lane] = z;
        out[1 + 2 * (size_t)Bn * Tn + (size_t)bs_[wid] * 3 + lane] = z;
    }
    __syncthreads();

    // hd -> slot 0 per batch (c carries over): two passes of 128 threads.
#pragma unroll
    for (int pass = 0; pass < 2; pass++) {
        int j = 2 * pass + (t >> 6), i = t & 63;
        ((float*)hb4[j][0])[i] = dec_linb[i]
            + dec_linW[i * 3 + 0] * sh_hz[j][0]
            + dec_linW[i * 3 + 1] * sh_hz[j][1]
            + dec_linW[i * 3 + 2] * sh_hz[j][2];
    }

    // Decoder weights, FOLDED: W' = dec_Whh + dec_Wih (x) outW,
    // b' = dec_b + dec_Wih*outb (shared by all batches).
    float wihA2 = dec_Wih[rA], wihB2 = dec_Wih[rB];
    {
        const float4* pA = (const float4*)(dec_Whh + rA * Hn);
        const float4* pB = (const float4*)(dec_Whh + rB * Hn);
#pragma unroll
        for (int k = 0; k < 16; k++) {
            float4 a = pA[k], c = pB[k], o = sh_ow4[k];
            wA[2 * k]     = pack2(__fmaf_rn(wihA2, o.x, a.x), __fmaf_rn(wihA2, o.y, a.y));
            wA[2 * k + 1] = pack2(__fmaf_rn(wihA2, o.z, a.z), __fmaf_rn(wihA2, o.w, a.w));
            wB[2 * k]     = pack2(__fmaf_rn(wihB2, o.x, c.x), __fmaf_rn(wihB2, o.y, c.y));
            wB[2 * k + 1] = pack2(__fmaf_rn(wihB2, o.z, c.z), __fmaf_rn(wihB2, o.w, c.w));
        }
    }
    float ob = outb[0];
    bsA = __fmaf_rn(wihA2, ob, dec_b[rA]);
    bsB = __fmaf_rn(wihB2, ob, dec_b[rB]);

    float ow0 = sh_ow[lane];
    float ow1 = sh_ow[lane + 32];
    __syncthreads();

    // qs_j = outW . hd_j + outb (step-0 correction: true x_0 = 0).
    float qs[NB] = {ob, ob, ob, ob};
    {
        const float* hd0 = (const float*)hb4[0][0];
        const float* hd1 = (const float*)hb4[1][0];
        const float* hd2 = (const float*)hb4[2][0];
        const float* hd3 = (const float*)hb4[3][0];
#pragma unroll 16
        for (int j = 0; j < Hn; j++) {
            float o = sh_ow[j];
            qs[0] = __fmaf_rn(o, hd0[j], qs[0]);
            qs[1] = __fmaf_rn(o, hd1[j], qs[1]);
            qs[2] = __fmaf_rn(o, hd2[j], qs[2]);
            qs[3] = __fmaf_rn(o, hd3[j], qs[3]);
        }
    }

    // ---- decoder: T steps; warp j emits y for batch j one step late ----
    float lacc = 0.0f;                     // lane0 of each warp

    for (int s = 0; s < Tn; s++) {
        // lagged y projection, off the recurrence critical path (all 4 warps)
        if (s > 0) {
            const float* hr = (const float*)hb4[wid][s & 1];
            float yp = hr[lane] * ow0 + hr[lane + 32] * ow1;
            yp += __shfl_xor_sync(0xffffffffu, yp, 16);
            yp += __shfl_xor_sync(0xffffffffu, yp, 8);
            yp += __shfl_xor_sync(0xffffffffu, yp, 4);
            yp += __shfl_xor_sync(0xffffffffu, yp, 2);
            yp += __shfl_xor_sync(0xffffffffu, yp, 1);
            if (lane == 0) {
                float y = yp + ob;
                out[1 + (size_t)Bn * Tn + (size_t)bs_[wid] * Tn + (s - 1)] = y;
                if (s - 1 < sl[wid]) {
                    float d = xbuf[wid][s - 1] - y;
                    lacc = __fmaf_rn(d, d, lacc);
                }
            }
        }

        const ulonglong2* hq0 = (const ulonglong2*)hb4[0][s & 1];
        const ulonglong2* hq1 = (const ulonglong2*)hb4[1][s & 1];
        const ulonglong2* hq2 = (const ulonglong2*)hb4[2][s & 1];
        const ulonglong2* hq3 = (const ulonglong2*)hb4[3][s & 1];

        unsigned long long aA[NB], aB[NB];
#pragma unroll
        for (int j = 0; j < NB; j++) { aA[j] = 0ull; aB[j] = 0ull; }

#pragma unroll
        for (int k = 0; k < 16; k++) {
            ulonglong2 h0 = hq0[k];
            ulonglong2 h1 = hq1[k];
            ulonglong2 h2 = hq2[k];
            ulonglong2 h3 = hq3[k];
            ffma2(aA[0], wA[2 * k], h0.x); ffma2(aB[0], wB[2 * k], h0.x);
            ffma2(aA[1], wA[2 * k], h1.x); ffma2(aB[1], wB[2 * k], h1.x);
            ffma2(aA[2], wA[2 * k], h2.x); ffma2(aB[2], wB[2 * k], h2.x);
            ffma2(aA[3], wA[2 * k], h3.x); ffma2(aB[3], wB[2 * k], h3.x);
            ffma2(aA[0], wA[2 * k + 1], h0.y); ffma2(aB[0], wB[2 * k + 1], h0.y);
            ffma2(aA[1], wA[2 * k + 1], h1.y); ffma2(aB[1], wB[2 * k + 1], h1.y);
            ffma2(aA[2], wA[2 * k + 1], h2.y); ffma2(aB[2], wB[2 * k + 1], h2.y);
            ffma2(aA[3], wA[2 * k + 1], h3.y); ffma2(aB[3], wB[2 * k + 1], h3.y);
        }

#pragma unroll
        for (int j = 0; j < NB; j++) {
            float lo, hi;
            unpack2(aA[j], lo, hi);
            float gA = (lo + hi) + bsA;
            unpack2(aB[j], lo, hi);
            float gB = (lo + hi) + bsB;
            if (s == 0) {                  // undo fold: x_0 = 0
                gA = __fmaf_rn(-wihA2, qs[j], gA);
                gB = __fmaf_rn(-wihB2, qs[j], gB);
            }

            float oA = __shfl_xor_sync(0xffffffffu, gA, 1);
            float oB = __shfl_xor_sync(0xffffffffu, gB, 1);
            float gi = even ? gA : oA;
            float gf = even ? gB : oB;
            float gg = even ? oA : gA;
            float go = even ? oB : gB;

            c_[j] = __fmaf_rn(sigm(gf), c_[j], sigm(gi) * tanh_hw(gg));
            if (even) ((float*)hb4[j][(s + 1) & 1])[u] = sigm(go) * tanh_hw(c_[j]);
        }
        __syncthreads();
    }

    // Tail: y_{T-1} from slot Tn&1 = 0 (warp j -> batch j).
    {
        const float* hr = (const float*)hb4[wid][Tn & 1];
        float yp = hr[lane] * ow0 + hr[lane + 32] * ow1;
        yp += __shfl_xor_sync(0xffffffffu, yp, 16);
        yp += __shfl_xor_sync(0xffffffffu, yp, 8);
        yp += __shfl_xor_sync(0xffffffffu, yp, 4);
        yp += __shfl_xor_sync(0xffffffffu, yp, 2);
        yp += __shfl_xor_sync(0xffffffffu, yp, 1);
        if (lane == 0) {
            float y = yp + ob;
            out[1 + (size_t)Bn * Tn + (size_t)bs_[wid] * Tn + (Tn - 1)] = y;
            if (Tn - 1 < sl[wid]) {
                float d = xbuf[wid][Tn - 1] - y;
                lacc = __fmaf_rn(d, d, lacc);
            }
            g_partial[bs_[wid]] = lacc;
        }
    }

    // ---- last-CTA deterministic loss finalize ----
    __threadfence();
    if (t == 0) s_last = atomicInc(&g_done, NCTA - 1);   // wraps to 0 each run
    __syncthreads();
    if (s_last == NCTA - 1) {
        __threadfence();
        double    s = 0.0;
        long long c = 0;
        for (int i = t; i < Bn; i += 128) {              // fixed order
            s += (double)g_partial[i];
            c += (long long)seq_lengths[i];
        }
        red_s[t] = s;
        red_c[t] = c;
        __syncthreads();
        for (int off = 64; off; off >>= 1) {             // fixed tree
            if (t < off) {
                red_s[t] += red_s[t + off];
                red_c[t] += red_c[t + off];
            }
            __syncthreads();
        }
        if (t == 0) out[0] = (float)(red_s[0] / (double)red_c[0]);
    }
}

extern "C" void kernel_launch(void* const* d_in, const int* in_sizes, int n_in,
                              void* d_out, int out_size) {
    const float* padded   = (const float*)d_in[0];
    const int*   seql     = (const int*)  d_in[1];
    const float* enc_Wih  = (const float*)d_in[2];
    const float* enc_Whh  = (const float*)d_in[3];
    const float* enc_b    = (const float*)d_in[4];
    const float* enc_linW = (const float*)d_in[5];
    const float* enc_linb = (const float*)d_in[6];
    const float* dec_linW = (const float*)d_in[7];
    const float* dec_linb = (const float*)d_in[8];
    const float* dec_Wih  = (const float*)d_in[9];
    const float* dec_Whh  = (const float*)d_in[10];
    const float* dec_b    = (const float*)d_in[11];
    const float* outW     = (const float*)d_in[12];
    const float* outb     = (const float*)d_in[13];
    float* out = (float*)d_out;

    sort_kernel<<<1, 1024>>>(seql);
    lstm_kernel<<<NCTA, 128>>>(padded, seql,
                               enc_Wih, enc_Whh, enc_b,
                               enc_linW, enc_linb,
                               dec_linW, dec_linb,
                               dec_Wih, dec_Whh, dec_b,
                               outW, outb, out);
}